// round 5
// baseline (speedup 1.0000x reference)
#include <cuda_runtime.h>

// SpikingAttentionJAX — two-kernel pipeline, latency-optimized.
// The sequential LIF scan collapses to per-token occurrence counts: updates to
// distinct vocab entries commute; entry t's final state depends only on
// (count n_t, v0[t]).
//
//   K1: histogram token_seq into g_count (all-zero on entry).
//   K2: ONE vocab entry per thread (500 blocks x 256 = 128000 exactly):
//       read count, re-zero inline (restores invariant for next graph replay),
//       replay n_t LIF steps, write gain (0.6 spiked / 1.0); warp-shuffle
//       top-5 of v_final, warp 0 merges to block top-5 -> g_cand; done-counter:
//       LAST-arriving block merges 2500 candidates and writes the 5 winners
//       (1.5). JAX top_k tie-break (lower index wins) via
//       key = (ordered_float(v) << 32) | ~index.

static constexpr float DECAY     = 0.7f;
static constexpr float THETA     = 1.0f;
static constexpr float GAIN_UP   = 1.5f;
static constexpr float GAIN_DOWN = 0.6f;
static constexpr int   KW   = 5;
static constexpr int   NT   = 256;
static constexpr int   NW   = NT / 32;
static constexpr int   MAXV = 131072;        // >= vocab (128000)
static constexpr int   MAXB = 512;           // >= K2 grid (500)

__device__ __align__(16) int g_count[MAXV];            // zero-init; kept zero
__device__ unsigned long long g_cand[MAXB * KW];
__device__ unsigned g_done = 0;                        // monotonic across replays

__device__ __forceinline__ unsigned ordered_bits(float f) {
    unsigned u = __float_as_uint(f);
    return (u & 0x80000000u) ? ~u : (u | 0x80000000u);
}

__device__ __forceinline__ unsigned long long warp_max(unsigned long long m) {
    #pragma unroll
    for (int off = 16; off > 0; off >>= 1) {
        unsigned long long o = __shfl_xor_sync(0xffffffffu, m, off);
        if (o > m) m = o;
    }
    return m;    // butterfly: all lanes hold the max
}

// ---------------------------------------------------------------- K1: histogram
__global__ void k_hist(const int* __restrict__ tok, int n, int vocab) {
    int i = blockIdx.x * blockDim.x + threadIdx.x;
    if (i < n) {
        int t = tok[i];
        t = t < 0 ? 0 : (t >= vocab ? vocab - 1 : t);
        atomicAdd(&g_count[t], 1);
    }
}

// ---------------------------------------------------------------- K2: gains + top-5
__global__ __launch_bounds__(NT)
void k_gains(const float* __restrict__ v0, float* __restrict__ out,
             int vocab, int nblocks) {
    const int tid  = threadIdx.x;
    const int lane = tid & 31;
    const int wid  = tid >> 5;
    const int i    = blockIdx.x * NT + tid;     // one vocab entry per thread

    __shared__ unsigned long long sw[NW * KW];
    __shared__ unsigned s_last;

    unsigned long long key = 0ull;
    if (i < vocab) {
        int   cnt = __ldcg(&g_count[i]);
        float v   = __ldg(&v0[i]);
        g_count[i] = 0;                          // restore invariant
        int s = 0;
        for (int it = 0; it < cnt; it++) {
            float vn = DECAY * v + 1.0f;
            if (vn >= THETA) { v = vn - THETA; s++; }
            else             { v = vn; }
        }
        out[i] = (s > 0) ? GAIN_DOWN : 1.0f;
        key = ((unsigned long long)ordered_bits(v) << 32)
            | (unsigned long long)(0xFFFFFFFFu - (unsigned)i);
    }

    // warp-local top-5 (pure shuffles)
    #pragma unroll
    for (int r = 0; r < KW; r++) {
        unsigned long long m = warp_max(key);
        if (lane == 0) sw[wid * KW + r] = m;
        if (key == m) key = 0ull;                // keys unique (index embedded)
    }
    __syncthreads();

    // warp 0: merge 40 warp candidates -> block top-5 -> g_cand
    if (wid == 0) {
        unsigned long long k0 = sw[lane];
        unsigned long long k1 = (lane < NW * KW - 32) ? sw[32 + lane] : 0ull;
        #pragma unroll
        for (int r = 0; r < KW; r++) {
            unsigned long long m = (k0 > k1) ? k0 : k1;
            m = warp_max(m);
            if (lane == 0) g_cand[blockIdx.x * KW + r] = m;
            if (k0 == m) k0 = 0ull;
            if (k1 == m) k1 = 0ull;
        }
    }

    // last-arriving block merges (detection only — no spinning)
    if (tid == 0) {
        __threadfence();                         // publish g_cand
        unsigned old = atomicAdd(&g_done, 1);
        s_last = (((old + 1) % (unsigned)nblocks) == 0u) ? 1u : 0u;
    }
    __syncthreads();
    if (!s_last) return;
    __threadfence();                             // acquire candidate writes

    const int ncand = nblocks * KW;              // 2500 for vocab=128000
    unsigned long long k[10];
    #pragma unroll
    for (int j = 0; j < 10; j++) {
        int c = tid + j * NT;
        k[j] = (c < ncand) ? __ldcg(&g_cand[c]) : 0ull;
    }

    __syncthreads();                             // sw reuse
    #pragma unroll
    for (int r = 0; r < KW; r++) {
        unsigned long long m = k[0];
        #pragma unroll
        for (int j = 1; j < 10; j++) if (k[j] > m) m = k[j];
        m = warp_max(m);
        if (lane == 0) sw[wid * KW + r] = m;
        #pragma unroll
        for (int j = 0; j < 10; j++) if (k[j] == m) k[j] = 0ull;
    }
    __syncthreads();

    if (wid == 0) {
        unsigned long long a0 = sw[lane];
        unsigned long long a1 = (lane < NW * KW - 32) ? sw[32 + lane] : 0ull;
        #pragma unroll
        for (int r = 0; r < KW; r++) {
            unsigned long long m = (a0 > a1) ? a0 : a1;
            m = warp_max(m);
            if (lane == 0 && m != 0ull) {
                unsigned idx = 0xFFFFFFFFu - (unsigned)(m & 0xFFFFFFFFull);
                out[idx] = GAIN_UP;
            }
            if (a0 == m) a0 = 0ull;
            if (a1 == m) a1 = 0ull;
        }
    }
}

// ---------------------------------------------------------------- launch
extern "C" void kernel_launch(void* const* d_in, const int* in_sizes, int n_in,
                              void* d_out, int out_size) {
    const int*   tok = (const int*)d_in[0];
    const float* v0  = (const float*)d_in[1];
    const int seq   = in_sizes[0];
    const int vocab = in_sizes[1];
    float* out = (float*)d_out;

    k_hist<<<(seq + NT - 1) / NT, NT>>>(tok, seq, vocab);

    int gblocks = (vocab + NT - 1) / NT;         // 500 for vocab=128000
    if (gblocks > MAXB) gblocks = MAXB;          // never hit at this size
    k_gains<<<gblocks, NT>>>(v0, out, vocab, gblocks);
}

// round 6
// speedup vs baseline: 1.0653x; 1.0653x over previous
#include <cuda_runtime.h>

// SpikingAttentionJAX — two kernels; top-k reductions rebuilt on HW REDUX.
// LIF scan collapses to per-token occurrence counts (updates to distinct vocab
// entries commute; entry t's final state depends only on count n_t and v0[t]).
//
//   K1: histogram token_seq -> g_count (all-zero on entry).
//   K2: one vocab entry/thread (500x256 = 128000 exactly): read count, re-zero
//       inline (invariant for next graph replay), replay n_t LIF steps, write
//       gain (0.6 spiked / 1.0). Top-5 of v_final via REDUX pairs:
//       round = REDUX.UMAX(value) then REDUX.UMIN(index) for the JAX
//       lower-index tie-break; warp -> block(warp0) -> last-arriving block
//       merges 2500 candidates and writes the 5 winners (1.5).

static constexpr float DECAY     = 0.7f;
static constexpr float THETA     = 1.0f;
static constexpr float GAIN_UP   = 1.5f;
static constexpr float GAIN_DOWN = 0.6f;
static constexpr int   KW   = 5;
static constexpr int   NT   = 256;
static constexpr int   NW   = NT / 32;
static constexpr int   MAXV = 131072;        // >= vocab (128000)
static constexpr int   MAXB = 512;           // >= K2 grid (500)

__device__ __align__(16) int g_count[MAXV];            // zero-init; kept zero
__device__ unsigned long long g_cand[MAXB * KW];
__device__ unsigned g_done = 0;                        // monotonic across replays

__device__ __forceinline__ unsigned ordered_bits(float f) {
    unsigned u = __float_as_uint(f);
    return (u & 0x80000000u) ? ~u : (u | 0x80000000u);  // >0 for any finite v
}

// ---------------------------------------------------------------- K1: histogram
__global__ void k_hist(const int* __restrict__ tok, int n, int vocab) {
    int i = blockIdx.x * blockDim.x + threadIdx.x;
    if (i < n) {
        int t = tok[i];
        t = t < 0 ? 0 : (t >= vocab ? vocab - 1 : t);
        atomicAdd(&g_count[t], 1);
    }
}

// ---------------------------------------------------------------- K2: gains + top-5
__global__ __launch_bounds__(NT)
void k_gains(const float* __restrict__ v0, float* __restrict__ out,
             int vocab, int nblocks) {
    const int tid  = threadIdx.x;
    const int lane = tid & 31;
    const int wid  = tid >> 5;
    const int i    = blockIdx.x * NT + tid;      // one vocab entry per thread

    __shared__ unsigned s_val[NW * KW];
    __shared__ unsigned s_idx[NW * KW];
    __shared__ unsigned long long s_w[NW];
    __shared__ unsigned long long s_best;
    __shared__ unsigned s_last;

    unsigned uval = 0u;                          // 0 = popped/invalid sentinel
    unsigned idx  = (unsigned)i;
    if (i < vocab) {
        int   cnt = g_count[i];
        float v   = __ldg(&v0[i]);
        g_count[i] = 0;                          // restore all-zero invariant
        int s = 0;
        for (int it = 0; it < cnt; it++) {
            float vn = DECAY * v + 1.0f;
            if (vn >= THETA) { v = vn - THETA; s++; }
            else             { v = vn; }
        }
        out[i] = (s > 0) ? GAIN_DOWN : 1.0f;
        uval = ordered_bits(v);
    }

    // ---- warp top-5: one REDUX.UMAX + one REDUX.UMIN per round ----
    #pragma unroll
    for (int r = 0; r < KW; r++) {
        unsigned m    = __reduce_max_sync(0xffffffffu, uval);
        unsigned cand = (uval == m) ? idx : 0xffffffffu;
        unsigned wi   = __reduce_min_sync(0xffffffffu, cand);  // lowest index wins
        if (lane == 0) { s_val[wid * KW + r] = m; s_idx[wid * KW + r] = wi; }
        if (uval == m && idx == wi) uval = 0u;   // pop exactly the winner
    }
    __syncthreads();

    // ---- warp 0: merge 40 (val,idx) pairs -> block top-5 -> g_cand ----
    if (wid == 0) {
        unsigned av = s_val[lane], ai = s_idx[lane];
        unsigned bv = (lane < NW * KW - 32) ? s_val[32 + lane] : 0u;
        unsigned bi = (lane < NW * KW - 32) ? s_idx[32 + lane] : 0xffffffffu;
        #pragma unroll
        for (int r = 0; r < KW; r++) {
            bool ta = (av > bv) || (av == bv && ai < bi);
            unsigned cv = ta ? av : bv;
            unsigned ci = ta ? ai : bi;
            unsigned m    = __reduce_max_sync(0xffffffffu, cv);
            unsigned cand = (cv == m) ? ci : 0xffffffffu;
            unsigned wi   = __reduce_min_sync(0xffffffffu, cand);
            if (lane == 0)
                g_cand[blockIdx.x * KW + r] =
                    ((unsigned long long)m << 32) |
                    (unsigned long long)(0xffffffffu - wi);   // monotone packed key
            if      (av == m && ai == wi) { av = 0u; ai = 0xffffffffu; }
            else if (bv == m && bi == wi) { bv = 0u; bi = 0xffffffffu; }
        }
    }

    // ---- last-arriving block merges (detection only; no spinning) ----
    if (tid == 0) {
        __threadfence();                         // publish g_cand
        unsigned old = atomicAdd(&g_done, 1);
        s_last = (((old + 1) % (unsigned)nblocks) == 0u) ? 1u : 0u;
    }
    __syncthreads();
    if (!s_last) return;
    __threadfence();                             // acquire candidate writes

    const int ncand = nblocks * KW;              // 2500
    unsigned long long k[10];
    #pragma unroll
    for (int j = 0; j < 10; j++) {
        int c = tid + j * NT;
        k[j] = (c < ncand) ? g_cand[c] : 0ull;
    }
    __syncthreads();

    #pragma unroll
    for (int r = 0; r < KW; r++) {
        unsigned long long m = k[0];
        #pragma unroll
        for (int j = 1; j < 10; j++) if (k[j] > m) m = k[j];
        // warp reduce the packed key via its 32-bit halves
        unsigned hv = (unsigned)(m >> 32);
        unsigned wm = __reduce_max_sync(0xffffffffu, hv);
        unsigned lo = (hv == wm) ? (unsigned)(m & 0xffffffffull) : 0u;
        unsigned wl = __reduce_max_sync(0xffffffffu, lo);   // max inv-idx = min idx
        if (lane == 0) s_w[wid] = ((unsigned long long)wm << 32) | wl;
        __syncthreads();
        if (tid == 0) {
            unsigned long long b = s_w[0];
            #pragma unroll
            for (int w = 1; w < NW; w++) if (s_w[w] > b) b = s_w[w];
            s_best = b;
            unsigned oidx = 0xffffffffu - (unsigned)(b & 0xffffffffull);
            out[oidx] = GAIN_UP;                 // >=5 real unique candidates exist
        }
        __syncthreads();
        unsigned long long b = s_best;
        #pragma unroll
        for (int j = 0; j < 10; j++) if (k[j] == b) k[j] = 0ull;
    }
}

// ---------------------------------------------------------------- launch
extern "C" void kernel_launch(void* const* d_in, const int* in_sizes, int n_in,
                              void* d_out, int out_size) {
    const int*   tok = (const int*)d_in[0];
    const float* v0  = (const float*)d_in[1];
    const int seq   = in_sizes[0];
    const int vocab = in_sizes[1];
    float* out = (float*)d_out;

    k_hist<<<(seq + NT - 1) / NT, NT>>>(tok, seq, vocab);

    int gblocks = (vocab + NT - 1) / NT;         // 500 for vocab=128000
    if (gblocks > MAXB) gblocks = MAXB;
    k_gains<<<gblocks, NT>>>(v0, out, vocab, gblocks);
}